// round 4
// baseline (speedup 1.0000x reference)
#include <cuda_runtime.h>
#include <cstdint>

typedef unsigned long long u64;

#define B_   4096
#define XD   128
#define YD   64
#define T_   200
#define LAT  100
#define G3   300
#define CH   50
#define R_   32
#define NB   (B_ / R_)     // 128 blocks
#define NT   1024          // 32 warps -> 8 per SMSP

// SMEM layout (float offsets). Dup buffers store each value twice at [.., 2r],[2r+1],
// stride 68, so a 64-bit LDS yields a ready-packed f32x2 broadcast operand.
#define OFF_BIH 0          // [300]
#define OFF_BHH 300        // [300]
#define OFF_BL1 600        // [104]
#define OFF_BL2 704        // [64]
#define OFF_H   768        // [100][68] dup   6800
#define OFF_AXD 7568       // [128][68] dup   8704
#define OFF_YP  16272      // [64][33]        2112
#define OFF_GX  18384      // [32][304]       9728
#define OFF_GHN 28112      // [32][104]       3328
#define OFF_WL1 31440      // [100][100]      10000
#define OFF_WL2 41440      // [100][64]       6400
#define OFF_O1D OFF_GX     // [100][68] dup, overlays GX (barrier-separated)
#define SMEM_FLOATS 47840  // 191360 bytes

__device__ __forceinline__ void fma2(u64 &d, u64 a, u64 b) {
    asm("fma.rn.f32x2 %0, %1, %2, %0;" : "+l"(d) : "l"(a), "l"(b));
}
__device__ __forceinline__ float2 unp(u64 v) {
    float2 f; asm("mov.b64 {%0, %1}, %2;" : "=f"(f.x), "=f"(f.y) : "l"(v));
    return f;
}
__device__ __forceinline__ float fsig(float x) {
    return __fdividef(1.0f, 1.0f + __expf(-x));
}
__device__ __forceinline__ float ftanh_(float x) {
    float e = __expf(2.0f * x);
    return 1.0f - __fdividef(2.0f, e + 1.0f);
}

extern "C" __global__ void __launch_bounds__(NT, 1) gru_kernel(
    const float* __restrict__ x, const float* __restrict__ y, const void* __restrict__ ymask,
    const float* __restrict__ Wmu1, const float* __restrict__ bmu1,
    const float* __restrict__ Wmu2, const float* __restrict__ bmu2,
    const float* __restrict__ Wih, const float* __restrict__ bih,
    const float* __restrict__ Whh, const float* __restrict__ bhh,
    const float* __restrict__ Wl1, const float* __restrict__ bl1,
    const float* __restrict__ Wl2, const float* __restrict__ bl2,
    const float* __restrict__ Wc1, const float* __restrict__ bc1,
    const float* __restrict__ Wc2, const float* __restrict__ bc2,
    float* __restrict__ out, int has_cls)
{
    extern __shared__ float sm[];
    const int tid  = threadIdx.x;
    const int lane = tid & 31;
    const int wid  = tid >> 5;        // 0..31
    const int role = wid >> 3;        // 0:r  1:z  2:nx  3:nh (2 of each per SMSP)
    const int q    = wid & 7;         // row quad 0..7
    const int r0   = q << 2;
    const int r2   = r0 << 1;         // dup index base
    const int b0   = blockIdx.x * R_;
    const int j0   = lane * 4;        // lanes<25 cover j=0..99 within a chunk

    // ---- stage biases + Wl1/Wl2; zero y_prev ----
    for (int i = tid; i < G3; i += NT) { sm[OFF_BIH + i] = bih[i]; sm[OFF_BHH + i] = bhh[i]; }
    for (int i = tid; i < LAT; i += NT) sm[OFF_BL1 + i] = bl1[i];
    for (int i = tid; i < YD;  i += NT) sm[OFF_BL2 + i] = bl2[i];
    for (int i = tid; i < (LAT * LAT) / 4; i += NT)
        ((float4*)(sm + OFF_WL1))[i] = __ldg(((const float4*)Wl1) + i);
    for (int i = tid; i < (LAT * YD) / 4; i += NT)
        ((float4*)(sm + OFF_WL2))[i] = __ldg(((const float4*)Wl2) + i);
    for (int i = tid; i < YD * 33; i += NT) sm[OFF_YP + i] = 0.f;

    // ---- mask dtype detection (uint8 / int32 / float32), deterministic ----
    const unsigned word = ((const unsigned*)ymask)[tid];
    const int big = __syncthreads_or((word & 0xFEFEFEFEu) != 0u);
    const int odd = __syncthreads_or((word & 0xFFFFFF00u) != 0u);
    const int mode = big ? 2 : (odd ? 0 : 1);

    // ---- stage x into AXD (dup) ----
#pragma unroll
    for (int i = 0; i < 4; i++) {
        const int e = tid + NT * i;       // 4096 = 32r x 128k
        const int r = e & 31, k = e >> 5;
        const float v = __ldg(&x[(size_t)(b0 + r) * XD + k]);
        *(float2*)&sm[OFF_AXD + k * 68 + 2 * r] = make_float2(v, v);
    }
    __syncthreads();

    // ---- h0: tmp = tanh(x @ Wmu1 + bmu1) -> O1D; h0 = tmp @ Wmu2 + bmu2 -> H ----
    // warp = row (32 warps, 32 rows); lanes<25 cover 100 cols, packed pairs
    if (lane < 25) {
        u64 acc0 = 0ull, acc1 = 0ull;
#pragma unroll 2
        for (int k = 0; k < XD; k++) {
            const u64 a = *(const u64*)&sm[OFF_AXD + k * 68 + 2 * wid];
            const ulonglong2 w = __ldg((const ulonglong2*)&Wmu1[k * LAT + j0]);
            fma2(acc0, a, w.x); fma2(acc1, a, w.y);
        }
        const float4 bb = __ldg((const float4*)&bmu1[j0]);
        const float2 v0 = unp(acc0), v1 = unp(acc1);
        const float o0 = ftanh_(v0.x + bb.x), o1 = ftanh_(v0.y + bb.y);
        const float o2 = ftanh_(v1.x + bb.z), o3 = ftanh_(v1.y + bb.w);
        *(float2*)&sm[OFF_O1D + (j0 + 0) * 68 + 2 * wid] = make_float2(o0, o0);
        *(float2*)&sm[OFF_O1D + (j0 + 1) * 68 + 2 * wid] = make_float2(o1, o1);
        *(float2*)&sm[OFF_O1D + (j0 + 2) * 68 + 2 * wid] = make_float2(o2, o2);
        *(float2*)&sm[OFF_O1D + (j0 + 3) * 68 + 2 * wid] = make_float2(o3, o3);
    }
    __syncthreads();
    if (lane < 25) {
        u64 acc0 = 0ull, acc1 = 0ull;
#pragma unroll 2
        for (int k = 0; k < LAT; k++) {
            const u64 a = *(const u64*)&sm[OFF_O1D + k * 68 + 2 * wid];
            const ulonglong2 w = __ldg((const ulonglong2*)&Wmu2[k * LAT + j0]);
            fma2(acc0, a, w.x); fma2(acc1, a, w.y);
        }
        const float4 bb = __ldg((const float4*)&bmu2[j0]);
        const float2 v0 = unp(acc0), v1 = unp(acc1);
        const float h0v = v0.x + bb.x, h1v = v0.y + bb.y;
        const float h2v = v1.x + bb.z, h3v = v1.y + bb.w;
        *(float2*)&sm[OFF_H + (j0 + 0) * 68 + 2 * wid] = make_float2(h0v, h0v);
        *(float2*)&sm[OFF_H + (j0 + 1) * 68 + 2 * wid] = make_float2(h1v, h1v);
        *(float2*)&sm[OFF_H + (j0 + 2) * 68 + 2 * wid] = make_float2(h2v, h2v);
        *(float2*)&sm[OFF_H + (j0 + 3) * 68 + 2 * wid] = make_float2(h3v, h3v);
    }

    // ---- prefetch y/mask for t=0 (2048 elems, 2 per thread) ----
    float yv[2], mfv[2];
    auto preload = [&](int t) {
#pragma unroll
        for (int i = 0; i < 2; i++) {
            const int e = tid + NT * i;
            const int r = e & 31, d = e >> 5;
            const size_t off = (size_t)(b0 + r) * (YD * T_) + (size_t)d * T_ + t;
            yv[i] = __ldg(&y[off]);
            float m;
            if (mode == 0)      m = (((const unsigned char*)ymask)[off] != 0) ? 1.f : 0.f;
            else if (mode == 1) m = (((const int*)ymask)[off] != 0) ? 1.f : 0.f;
            else                m = (((const float*)ymask)[off] != 0.f) ? 1.f : 0.f;
            mfv[i] = m;
        }
    };
    preload(0);
    __syncthreads();

    // ================= main recurrence =================
    for (int t = 0; t < T_; ++t) {
        // -- teacher forcing -> AXD (dup, k interleaved value/mask) --
#pragma unroll
        for (int i = 0; i < 2; i++) {
            const int e = tid + NT * i;
            const int r = e & 31, d = e >> 5;
            const float m  = mfv[i];
            const float yp = sm[OFF_YP + d * 33 + r];
            const float yin = (m != 0.f) ? yv[i] : yp;
            *(float2*)&sm[OFF_AXD + (2 * d) * 68 + 2 * r]     = make_float2(yin, yin);
            *(float2*)&sm[OFF_AXD + (2 * d + 1) * 68 + 2 * r] = make_float2(m, m);
        }
        if (t + 1 < T_) preload(t + 1);
        __syncthreads();

        // -- fused GEMM1 (ax@Wih) + GEMM2 (h@Whh) by role, FFMA2 --
        if (lane < 25) {
            u64 acc[4][2];
#pragma unroll
            for (int i = 0; i < 4; i++) { acc[i][0] = 0ull; acc[i][1] = 0ull; }

            if (role < 3) {
                // x-side (roles r, z, nx): k over 128, Wih chunk role*100
                const float* Wp = Wih + role * 100 + j0;
#pragma unroll 2
                for (int k = 0; k < XD; k++) {
                    const ulonglong2 a01 = *(const ulonglong2*)&sm[OFF_AXD + k * 68 + r2];
                    const ulonglong2 a23 = *(const ulonglong2*)&sm[OFF_AXD + k * 68 + r2 + 4];
                    const ulonglong2 w = __ldg((const ulonglong2*)&Wp[k * G3]);
                    fma2(acc[0][0], a01.x, w.x); fma2(acc[0][1], a01.x, w.y);
                    fma2(acc[1][0], a01.y, w.x); fma2(acc[1][1], a01.y, w.y);
                    fma2(acc[2][0], a23.x, w.x); fma2(acc[2][1], a23.x, w.y);
                    fma2(acc[3][0], a23.y, w.x); fma2(acc[3][1], a23.y, w.y);
                }
            }
            if (role == 0 || role == 1 || role == 3) {
                // h-side (roles r, z, nh): k over 100, Whh streamed from L2
                const int co = (role == 3) ? 200 : role * 100;
                const float* Wp = Whh + co + j0;
#pragma unroll 2
                for (int k = 0; k < LAT; k++) {
                    const ulonglong2 a01 = *(const ulonglong2*)&sm[OFF_H + k * 68 + r2];
                    const ulonglong2 a23 = *(const ulonglong2*)&sm[OFF_H + k * 68 + r2 + 4];
                    const ulonglong2 w = __ldg((const ulonglong2*)&Wp[k * G3]);
                    fma2(acc[0][0], a01.x, w.x); fma2(acc[0][1], a01.x, w.y);
                    fma2(acc[1][0], a01.y, w.x); fma2(acc[1][1], a01.y, w.y);
                    fma2(acc[2][0], a23.x, w.x); fma2(acc[2][1], a23.x, w.y);
                    fma2(acc[3][0], a23.y, w.x); fma2(acc[3][1], a23.y, w.y);
                }
            }
            // store partials (u64 pair = float4, bit-identical layout)
            if (role < 3) {
                const int co = role * 100;
#pragma unroll
                for (int i = 0; i < 4; i++) {
                    ulonglong2 v; v.x = acc[i][0]; v.y = acc[i][1];
                    *(ulonglong2*)&sm[OFF_GX + (r0 + i) * 304 + co + j0] = v;
                }
            } else {
#pragma unroll
                for (int i = 0; i < 4; i++) {
                    ulonglong2 v; v.x = acc[i][0]; v.y = acc[i][1];
                    *(ulonglong2*)&sm[OFF_GHN + (r0 + i) * 104 + j0] = v;
                }
            }
        }
        __syncthreads();

        // -- gates: r,z = sigmoid; n = tanh(gxn + r*ghn); h = (1-z)*n + z*h --
#pragma unroll
        for (int it = 0; it < 4; ++it) {
            const int idx = tid + NT * it;
            if (idx < R_ * LAT) {
                const int r = idx / LAT;
                const int j = idx - r * LAT;
                const float g_r = sm[OFF_GX + r * 304 + j]       + sm[OFF_BIH + j]       + sm[OFF_BHH + j];
                const float g_z = sm[OFF_GX + r * 304 + 100 + j] + sm[OFF_BIH + 100 + j] + sm[OFF_BHH + 100 + j];
                const float gxn = sm[OFF_GX + r * 304 + 200 + j] + sm[OFF_BIH + 200 + j];
                const float ghn = sm[OFF_GHN + r * 104 + j]      + sm[OFF_BHH + 200 + j];
                const float rg = fsig(g_r);
                const float z  = fsig(g_z);
                const float n  = ftanh_(gxn + rg * ghn);
                const float hd = sm[OFF_H + j * 68 + 2 * r];
                const float hn = (1.f - z) * n + z * hd;
                *(float2*)&sm[OFF_H + j * 68 + 2 * r] = make_float2(hn, hn);
            }
        }
        __syncthreads();

        // -- GEMM3: o1 = tanh(h @ Wl1 + bl1); warp = row, FFMA2, W in SMEM --
        if (lane < 25) {
            u64 acc0 = 0ull, acc1 = 0ull;
#pragma unroll 4
            for (int k = 0; k < LAT; k++) {
                const u64 a = *(const u64*)&sm[OFF_H + k * 68 + 2 * wid];
                const ulonglong2 w = *(const ulonglong2*)&sm[OFF_WL1 + k * LAT + j0];
                fma2(acc0, a, w.x); fma2(acc1, a, w.y);
            }
            const float4 bb = *(const float4*)&sm[OFF_BL1 + j0];
            const float2 v0 = unp(acc0), v1 = unp(acc1);
            const float o0 = ftanh_(v0.x + bb.x), o1 = ftanh_(v0.y + bb.y);
            const float o2 = ftanh_(v1.x + bb.z), o3 = ftanh_(v1.y + bb.w);
            *(float2*)&sm[OFF_O1D + (j0 + 0) * 68 + 2 * wid] = make_float2(o0, o0);
            *(float2*)&sm[OFF_O1D + (j0 + 1) * 68 + 2 * wid] = make_float2(o1, o1);
            *(float2*)&sm[OFF_O1D + (j0 + 2) * 68 + 2 * wid] = make_float2(o2, o2);
            *(float2*)&sm[OFF_O1D + (j0 + 3) * 68 + 2 * wid] = make_float2(o3, o3);
        }
        __syncthreads();

        // -- GEMM4: out_t = o1 @ Wl2 + bl2; warp = row, lanes<16, FFMA2 --
        if (lane < 16) {
            u64 acc0 = 0ull, acc1 = 0ull;
#pragma unroll 4
            for (int k = 0; k < LAT; k++) {
                const u64 a = *(const u64*)&sm[OFF_O1D + k * 68 + 2 * wid];
                const ulonglong2 w = *(const ulonglong2*)&sm[OFF_WL2 + k * YD + j0];
                fma2(acc0, a, w.x); fma2(acc1, a, w.y);
            }
            const float4 bb = *(const float4*)&sm[OFF_BL2 + j0];
            const float2 v0 = unp(acc0), v1 = unp(acc1);
            const float v[4] = {v0.x + bb.x, v0.y + bb.y, v1.x + bb.z, v1.y + bb.w};
            float* op = out + (size_t)(b0 + wid) * (YD * T_) + (size_t)j0 * T_ + t;
#pragma unroll
            for (int c = 0; c < 4; c++) {
                op[(size_t)c * T_] = v[c];
                sm[OFF_YP + (j0 + c) * 33 + wid] = v[c];
            }
        }
        __syncthreads();
    }

    // ---- classifier: sigmoid(relu(h_T @ Wc1 + bc1) @ Wc2 + bc2) ----
    if (has_cls) {
        for (int idx = tid; idx < R_ * CH; idx += NT) {
            const int r = idx & 31, c = idx >> 5;
            float acc = __ldg(&bc1[c]);
            for (int k = 0; k < LAT; k++)
                acc = fmaf(sm[OFF_H + k * 68 + 2 * r], __ldg(&Wc1[k * CH + c]), acc);
            sm[OFF_GHN + c * 36 + r] = fmaxf(acc, 0.f);
        }
        __syncthreads();
        if (tid < R_) {
            float acc = __ldg(&bc2[0]);
            for (int c = 0; c < CH; c++)
                acc = fmaf(sm[OFF_GHN + c * 36 + tid], __ldg(&Wc2[c]), acc);
            out[(size_t)B_ * YD * T_ + b0 + tid] = fsig(acc);
        }
    }
}

extern "C" void kernel_launch(void* const* d_in, const int* in_sizes, int n_in,
                              void* d_out, int out_size)
{
    cudaFuncSetAttribute(gru_kernel, cudaFuncAttributeMaxDynamicSharedMemorySize,
                         SMEM_FLOATS * (int)sizeof(float));
    const int has_cls = (out_size > B_ * YD * T_) ? 1 : 0;
    gru_kernel<<<NB, NT, SMEM_FLOATS * sizeof(float)>>>(
        (const float*)d_in[0],   // x
        (const float*)d_in[1],   // y
        d_in[2],                 // y_mask (dtype auto-detected)
        (const float*)d_in[3],  (const float*)d_in[4],   // Wmu1, bmu1
        (const float*)d_in[5],  (const float*)d_in[6],   // Wmu2, bmu2
        (const float*)d_in[11], (const float*)d_in[12],  // Wih, bih
        (const float*)d_in[13], (const float*)d_in[14],  // Whh, bhh
        (const float*)d_in[15], (const float*)d_in[16],  // Wl1, bl1
        (const float*)d_in[17], (const float*)d_in[18],  // Wl2, bl2
        (const float*)d_in[19], (const float*)d_in[20],  // Wc1, bc1
        (const float*)d_in[21], (const float*)d_in[22],  // Wc2, bc2
        (float*)d_out, has_cls);
}

// round 5
// speedup vs baseline: 1.1723x; 1.1723x over previous
#include <cuda_runtime.h>
#include <cstdint>

#define B_   4096
#define XD   128
#define YD   64
#define T_   200
#define LAT  100
#define G3   300
#define CH   50
#define R_   16
#define NB   (B_ / R_)     // 256 blocks -> 2 per SM
#define NT   512           // 16 warps/block; 2 blocks/SM -> 8 warps/SMSP

// SMEM layout (float offsets), per block: 22428 floats = 89712 bytes
#define OFF_BIH 0          // [300]
#define OFF_BHH 300        // [300]
#define OFF_BL1 600        // [100]
#define OFF_BL2 700        // [64]
#define OFF_H   764        // [100][20]  ([k][r])   2000
#define OFF_AX  2764       // [128][16]  ([k][r])   2048
#define OFF_YP  4812       // [64][17]   ([d][r])   1088
#define OFF_GX  5900       // [16][304]  ([r][j])   4864
#define OFF_GHN 10764      // [16][104]  ([r][j])   1664
#define OFF_WL1 12428      // [100][100]            10000
#define OFF_O1  OFF_GX     // [100][20] overlays GX (barrier-separated)
#define SMEM_FLOATS 22428

__device__ __forceinline__ float fsig(float x) {
    return __fdividef(1.0f, 1.0f + __expf(-x));
}
__device__ __forceinline__ float ftanh_(float x) {
    float e = __expf(2.0f * x);
    return 1.0f - __fdividef(2.0f, e + 1.0f);
}

extern "C" __global__ void __launch_bounds__(NT, 2) gru_kernel(
    const float* __restrict__ x, const float* __restrict__ y, const void* __restrict__ ymask,
    const float* __restrict__ Wmu1, const float* __restrict__ bmu1,
    const float* __restrict__ Wmu2, const float* __restrict__ bmu2,
    const float* __restrict__ Wih, const float* __restrict__ bih,
    const float* __restrict__ Whh, const float* __restrict__ bhh,
    const float* __restrict__ Wl1, const float* __restrict__ bl1,
    const float* __restrict__ Wl2, const float* __restrict__ bl2,
    const float* __restrict__ Wc1, const float* __restrict__ bc1,
    const float* __restrict__ Wc2, const float* __restrict__ bc2,
    float* __restrict__ out, int has_cls)
{
    extern __shared__ float sm[];
    const int tid  = threadIdx.x;
    const int lane = tid & 31;
    const int wid  = tid >> 5;        // 0..15
    const int role = wid >> 2;        // 0:r 1:z 2:nx 3:nh (one of each per SMSP per block)
    const int r0   = (wid & 3) << 2;  // row quad base within 16 rows
    const int b0   = blockIdx.x * R_;
    const int j0   = lane * 4;        // lanes<25 cover 100 cols

    // ---- stage biases + Wl1; zero y_prev ----
    for (int i = tid; i < G3; i += NT) { sm[OFF_BIH + i] = bih[i]; sm[OFF_BHH + i] = bhh[i]; }
    for (int i = tid; i < LAT; i += NT) sm[OFF_BL1 + i] = bl1[i];
    for (int i = tid; i < YD;  i += NT) sm[OFF_BL2 + i] = bl2[i];
    for (int i = tid; i < (LAT * LAT) / 4; i += NT)
        ((float4*)(sm + OFF_WL1))[i] = __ldg(((const float4*)Wl1) + i);
    for (int i = tid; i < YD * 17; i += NT) sm[OFF_YP + i] = 0.f;

    // ---- mask dtype detection (uint8 / int32 / float32), deterministic ----
    const unsigned word = ((const unsigned*)ymask)[tid];
    const int big = __syncthreads_or((word & 0xFEFEFEFEu) != 0u);  // any byte > 1 -> f32
    const int odd = __syncthreads_or((word & 0xFFFFFF00u) != 0u);  // upper bytes set -> u8
    const int mode = big ? 2 : (odd ? 0 : 1);

    // ---- stage x into AX ([k][16]) ----
#pragma unroll
    for (int i = 0; i < 4; i++) {
        const int e = tid + NT * i;       // 2048 = 16r x 128k
        const int r = e & 15, k = e >> 4;
        sm[OFF_AX + k * 16 + r] = __ldg(&x[(size_t)(b0 + r) * XD + k]);
    }
    __syncthreads();

    // ---- h0: tmp = tanh(x @ Wmu1 + bmu1) -> O1; h0 = tmp @ Wmu2 + bmu2 -> H ----
    // warp = row (16 warps = 16 rows), lanes<25 cover 100 cols
    if (lane < 25) {
        float acc[4] = {0.f, 0.f, 0.f, 0.f};
#pragma unroll 4
        for (int k = 0; k < XD; k++) {
            const float a = sm[OFF_AX + k * 16 + wid];
            const float4 wv = __ldg((const float4*)&Wmu1[k * LAT + j0]);
            acc[0] = fmaf(a, wv.x, acc[0]); acc[1] = fmaf(a, wv.y, acc[1]);
            acc[2] = fmaf(a, wv.z, acc[2]); acc[3] = fmaf(a, wv.w, acc[3]);
        }
        const float4 bb = __ldg((const float4*)&bmu1[j0]);
        sm[OFF_O1 + (j0 + 0) * 20 + wid] = ftanh_(acc[0] + bb.x);
        sm[OFF_O1 + (j0 + 1) * 20 + wid] = ftanh_(acc[1] + bb.y);
        sm[OFF_O1 + (j0 + 2) * 20 + wid] = ftanh_(acc[2] + bb.z);
        sm[OFF_O1 + (j0 + 3) * 20 + wid] = ftanh_(acc[3] + bb.w);
    }
    __syncthreads();
    if (lane < 25) {
        float acc[4] = {0.f, 0.f, 0.f, 0.f};
#pragma unroll 4
        for (int k = 0; k < LAT; k++) {
            const float a = sm[OFF_O1 + k * 20 + wid];
            const float4 wv = __ldg((const float4*)&Wmu2[k * LAT + j0]);
            acc[0] = fmaf(a, wv.x, acc[0]); acc[1] = fmaf(a, wv.y, acc[1]);
            acc[2] = fmaf(a, wv.z, acc[2]); acc[3] = fmaf(a, wv.w, acc[3]);
        }
        const float4 bb = __ldg((const float4*)&bmu2[j0]);
        sm[OFF_H + (j0 + 0) * 20 + wid] = acc[0] + bb.x;
        sm[OFF_H + (j0 + 1) * 20 + wid] = acc[1] + bb.y;
        sm[OFF_H + (j0 + 2) * 20 + wid] = acc[2] + bb.z;
        sm[OFF_H + (j0 + 3) * 20 + wid] = acc[3] + bb.w;
    }

    // ---- prefetch y/mask for t=0 (1024 = 16r x 64d, 2 per thread) ----
    float yv[2], mfv[2];
    auto preload = [&](int t) {
#pragma unroll
        for (int i = 0; i < 2; i++) {
            const int e = tid + NT * i;
            const int r = e & 15, d = e >> 4;
            const size_t off = (size_t)(b0 + r) * (YD * T_) + (size_t)d * T_ + t;
            yv[i] = __ldg(&y[off]);
            float m;
            if (mode == 0)      m = (((const unsigned char*)ymask)[off] != 0) ? 1.f : 0.f;
            else if (mode == 1) m = (((const int*)ymask)[off] != 0) ? 1.f : 0.f;
            else                m = (((const float*)ymask)[off] != 0.f) ? 1.f : 0.f;
            mfv[i] = m;
        }
    };
    preload(0);
    __syncthreads();

    // ================= main recurrence =================
    for (int t = 0; t < T_; ++t) {
        // -- teacher forcing -> AX ([k][16], k interleaved value/mask) --
#pragma unroll
        for (int i = 0; i < 2; i++) {
            const int e = tid + NT * i;
            const int r = e & 15, d = e >> 4;
            const float m  = mfv[i];
            const float yp = sm[OFF_YP + d * 17 + r];
            const float yin = (m != 0.f) ? yv[i] : yp;
            sm[OFF_AX + (2 * d) * 16 + r]     = yin;
            sm[OFF_AX + (2 * d + 1) * 16 + r] = m;
        }
        if (t + 1 < T_) preload(t + 1);
        __syncthreads();

        // -- fused GEMM1 (ax@Wih) + GEMM2 (h@Whh) by role --
        if (lane < 25) {
            float acc[4][4];
#pragma unroll
            for (int i = 0; i < 4; i++)
#pragma unroll
                for (int c = 0; c < 4; c++) acc[i][c] = 0.f;

            if (role < 3) {
                // x-side (roles r, z, nx): k over 128
                const float* Wp = Wih + role * 100 + j0;
#pragma unroll 4
                for (int k = 0; k < XD; k++) {
                    const float4 a = *(const float4*)&sm[OFF_AX + k * 16 + r0];
                    const float4 wv = __ldg((const float4*)&Wp[k * G3]);
                    acc[0][0] = fmaf(a.x, wv.x, acc[0][0]); acc[0][1] = fmaf(a.x, wv.y, acc[0][1]);
                    acc[0][2] = fmaf(a.x, wv.z, acc[0][2]); acc[0][3] = fmaf(a.x, wv.w, acc[0][3]);
                    acc[1][0] = fmaf(a.y, wv.x, acc[1][0]); acc[1][1] = fmaf(a.y, wv.y, acc[1][1]);
                    acc[1][2] = fmaf(a.y, wv.z, acc[1][2]); acc[1][3] = fmaf(a.y, wv.w, acc[1][3]);
                    acc[2][0] = fmaf(a.z, wv.x, acc[2][0]); acc[2][1] = fmaf(a.z, wv.y, acc[2][1]);
                    acc[2][2] = fmaf(a.z, wv.z, acc[2][2]); acc[2][3] = fmaf(a.z, wv.w, acc[2][3]);
                    acc[3][0] = fmaf(a.w, wv.x, acc[3][0]); acc[3][1] = fmaf(a.w, wv.y, acc[3][1]);
                    acc[3][2] = fmaf(a.w, wv.z, acc[3][2]); acc[3][3] = fmaf(a.w, wv.w, acc[3][3]);
                }
            }
            if (role != 2) {
                // h-side (roles r, z, nh): k over 100
                const int co = (role == 3) ? 200 : role * 100;
                const float* Wp = Whh + co + j0;
#pragma unroll 4
                for (int k = 0; k < LAT; k++) {
                    const float4 a = *(const float4*)&sm[OFF_H + k * 20 + r0];
                    const float4 wv = __ldg((const float4*)&Wp[k * G3]);
                    acc[0][0] = fmaf(a.x, wv.x, acc[0][0]); acc[0][1] = fmaf(a.x, wv.y, acc[0][1]);
                    acc[0][2] = fmaf(a.x, wv.z, acc[0][2]); acc[0][3] = fmaf(a.x, wv.w, acc[0][3]);
                    acc[1][0] = fmaf(a.y, wv.x, acc[1][0]); acc[1][1] = fmaf(a.y, wv.y, acc[1][1]);
                    acc[1][2] = fmaf(a.y, wv.z, acc[1][2]); acc[1][3] = fmaf(a.y, wv.w, acc[1][3]);
                    acc[2][0] = fmaf(a.z, wv.x, acc[2][0]); acc[2][1] = fmaf(a.z, wv.y, acc[2][1]);
                    acc[2][2] = fmaf(a.z, wv.z, acc[2][2]); acc[2][3] = fmaf(a.z, wv.w, acc[2][3]);
                    acc[3][0] = fmaf(a.w, wv.x, acc[3][0]); acc[3][1] = fmaf(a.w, wv.y, acc[3][1]);
                    acc[3][2] = fmaf(a.w, wv.z, acc[3][2]); acc[3][3] = fmaf(a.w, wv.w, acc[3][3]);
                }
            }
            if (role < 3) {
                const int co = role * 100;
#pragma unroll
                for (int i = 0; i < 4; i++)
                    *(float4*)&sm[OFF_GX + (r0 + i) * 304 + co + j0] =
                        make_float4(acc[i][0], acc[i][1], acc[i][2], acc[i][3]);
            } else {
#pragma unroll
                for (int i = 0; i < 4; i++)
                    *(float4*)&sm[OFF_GHN + (r0 + i) * 104 + j0] =
                        make_float4(acc[i][0], acc[i][1], acc[i][2], acc[i][3]);
            }
        }
        __syncthreads();

        // -- gates: r,z = sigmoid; n = tanh(gxn + r*ghn); h = (1-z)*n + z*h --
#pragma unroll
        for (int it = 0; it < 4; ++it) {
            const int idx = tid + NT * it;    // 1600 = 16r x 100j
            if (idx < R_ * LAT) {
                const int r = idx / LAT;
                const int j = idx - r * LAT;
                const float g_r = sm[OFF_GX + r * 304 + j]       + sm[OFF_BIH + j]       + sm[OFF_BHH + j];
                const float g_z = sm[OFF_GX + r * 304 + 100 + j] + sm[OFF_BIH + 100 + j] + sm[OFF_BHH + 100 + j];
                const float gxn = sm[OFF_GX + r * 304 + 200 + j] + sm[OFF_BIH + 200 + j];
                const float ghn = sm[OFF_GHN + r * 104 + j]      + sm[OFF_BHH + 200 + j];
                const float rg = fsig(g_r);
                const float z  = fsig(g_z);
                const float n  = ftanh_(gxn + rg * ghn);
                const float hd = sm[OFF_H + j * 20 + r];
                sm[OFF_H + j * 20 + r] = (1.f - z) * n + z * hd;
            }
        }
        __syncthreads();

        // -- GEMM3: o1 = tanh(h @ Wl1 + bl1); warp = row, Wl1 in SMEM --
        if (lane < 25) {
            float acc[4] = {0.f, 0.f, 0.f, 0.f};
#pragma unroll 4
            for (int k = 0; k < LAT; k++) {
                const float a = sm[OFF_H + k * 20 + wid];
                const float4 wv = *(const float4*)&sm[OFF_WL1 + k * LAT + j0];
                acc[0] = fmaf(a, wv.x, acc[0]); acc[1] = fmaf(a, wv.y, acc[1]);
                acc[2] = fmaf(a, wv.z, acc[2]); acc[3] = fmaf(a, wv.w, acc[3]);
            }
            const float4 bb = *(const float4*)&sm[OFF_BL1 + j0];
            sm[OFF_O1 + (j0 + 0) * 20 + wid] = ftanh_(acc[0] + bb.x);
            sm[OFF_O1 + (j0 + 1) * 20 + wid] = ftanh_(acc[1] + bb.y);
            sm[OFF_O1 + (j0 + 2) * 20 + wid] = ftanh_(acc[2] + bb.z);
            sm[OFF_O1 + (j0 + 3) * 20 + wid] = ftanh_(acc[3] + bb.w);
        }
        __syncthreads();

        // -- GEMM4: out_t = o1 @ Wl2 + bl2; warp = 4 cols, all lanes active --
        {
            const int row = lane & 15;                      // 0..15
            const int jc  = (wid << 2) + ((lane >> 4) << 1);// wid*4 + half*2
            float a0 = 0.f, a1 = 0.f;
#pragma unroll 4
            for (int k = 0; k < LAT; k++) {
                const float a = sm[OFF_O1 + k * 20 + row];
                const float2 wv = __ldg((const float2*)&Wl2[k * YD + jc]);
                a0 = fmaf(a, wv.x, a0); a1 = fmaf(a, wv.y, a1);
            }
            const float v0 = a0 + sm[OFF_BL2 + jc];
            const float v1 = a1 + sm[OFF_BL2 + jc + 1];
            float* op = out + (size_t)(b0 + row) * (YD * T_) + (size_t)jc * T_ + t;
            op[0]  = v0;
            op[T_] = v1;
            sm[OFF_YP + jc * 17 + row]       = v0;
            sm[OFF_YP + (jc + 1) * 17 + row] = v1;
        }
        __syncthreads();
    }

    // ---- classifier: sigmoid(relu(h_T @ Wc1 + bc1) @ Wc2 + bc2) ----
    if (has_cls) {
        for (int idx = tid; idx < R_ * CH; idx += NT) {     // 800 = 16r x 50c
            const int r = idx & 15, c = idx >> 4;
            float acc = __ldg(&bc1[c]);
            for (int k = 0; k < LAT; k++)
                acc = fmaf(sm[OFF_H + k * 20 + r], __ldg(&Wc1[k * CH + c]), acc);
            sm[OFF_GHN + c * 16 + r] = fmaxf(acc, 0.f);
        }
        __syncthreads();
        if (tid < R_) {
            float acc = __ldg(&bc2[0]);
            for (int c = 0; c < CH; c++)
                acc = fmaf(sm[OFF_GHN + c * 16 + tid], __ldg(&Wc2[c]), acc);
            out[(size_t)B_ * YD * T_ + b0 + tid] = fsig(acc);
        }
    }
}

extern "C" void kernel_launch(void* const* d_in, const int* in_sizes, int n_in,
                              void* d_out, int out_size)
{
    cudaFuncSetAttribute(gru_kernel, cudaFuncAttributeMaxDynamicSharedMemorySize,
                         SMEM_FLOATS * (int)sizeof(float));
    const int has_cls = (out_size > B_ * YD * T_) ? 1 : 0;
    gru_kernel<<<NB, NT, SMEM_FLOATS * sizeof(float)>>>(
        (const float*)d_in[0],   // x
        (const float*)d_in[1],   // y
        d_in[2],                 // y_mask (dtype auto-detected)
        (const float*)d_in[3],  (const float*)d_in[4],   // Wmu1, bmu1
        (const float*)d_in[5],  (const float*)d_in[6],   // Wmu2, bmu2
        (const float*)d_in[11], (const float*)d_in[12],  // Wih, bih
        (const float*)d_in[13], (const float*)d_in[14],  // Whh, bhh
        (const float*)d_in[15], (const float*)d_in[16],  // Wl1, bl1
        (const float*)d_in[17], (const float*)d_in[18],  // Wl2, bl2
        (const float*)d_in[19], (const float*)d_in[20],  // Wc1, bc1
        (const float*)d_in[21], (const float*)d_in[22],  // Wc2, bc2
        (float*)d_out, has_cls);
}

// round 6
// speedup vs baseline: 1.6168x; 1.3792x over previous
#include <cuda_runtime.h>
#include <cstdint>

#define B_   4096
#define XD   128
#define YD   64
#define T_   200
#define LAT  100
#define G3   300
#define CH   50
#define NBK  296           // 2 blocks per SM on 148 SMs, exactly balanced
#define NT   512           // 16 warps/block; 2 blocks/SM -> 8 warps/SMSP

// SMEM layout (float offsets), per block: 27420 floats = 109680 bytes
#define OFF_BIH 0          // [300]
#define OFF_BHH 300        // [300]
#define OFF_BL1 600        // [100]
#define OFF_BL2 700        // [64]
#define OFF_H   764        // [100][20]  ([k][r])   2000
#define OFF_AX  2764       // [128][16]  ([k][r])   2048
#define OFF_YP  4812       // [64][17]   ([d][r])   1088
#define OFF_GX  5900       // [16][304]  ([r][j])   4864
#define OFF_GHN 10764      // [16][104]  ([r][j])   1664
#define OFF_P2  12428      // [16][104]  h_r[44,88)  1664
#define OFF_P4  14092      // [16][104]  h_z[44,100) 1664
#define OFF_P5  15756      // [16][104]  h_r[88,100) 1664
#define OFF_WL1 17420      // [100][100]            10000
#define OFF_O1  OFF_GX     // [100][20] overlays GX (barrier-separated)
#define SMEM_FLOATS 27420

__device__ __forceinline__ float fsig(float x) {
    return __fdividef(1.0f, 1.0f + __expf(-x));
}
__device__ __forceinline__ float ftanh_(float x) {
    float e = __expf(2.0f * x);
    return 1.0f - __fdividef(2.0f, e + 1.0f);
}

// accumulate quad-tile over A in SMEM (stride lda) for k in [k0,k1), W in gmem stride G3
__device__ __forceinline__ void accum(
    float acc[4][4], const float* __restrict__ sa, int lda, int r0,
    const float* __restrict__ Wp, int k0, int k1)
{
#pragma unroll 4
    for (int k = k0; k < k1; k++) {
        const float4 a = *(const float4*)&sa[k * lda + r0];
        const float4 wv = __ldg((const float4*)&Wp[k * G3]);
        acc[0][0] = fmaf(a.x, wv.x, acc[0][0]); acc[0][1] = fmaf(a.x, wv.y, acc[0][1]);
        acc[0][2] = fmaf(a.x, wv.z, acc[0][2]); acc[0][3] = fmaf(a.x, wv.w, acc[0][3]);
        acc[1][0] = fmaf(a.y, wv.x, acc[1][0]); acc[1][1] = fmaf(a.y, wv.y, acc[1][1]);
        acc[1][2] = fmaf(a.y, wv.z, acc[1][2]); acc[1][3] = fmaf(a.y, wv.w, acc[1][3]);
        acc[2][0] = fmaf(a.z, wv.x, acc[2][0]); acc[2][1] = fmaf(a.z, wv.y, acc[2][1]);
        acc[2][2] = fmaf(a.z, wv.z, acc[2][2]); acc[2][3] = fmaf(a.z, wv.w, acc[2][3]);
        acc[3][0] = fmaf(a.w, wv.x, acc[3][0]); acc[3][1] = fmaf(a.w, wv.y, acc[3][1]);
        acc[3][2] = fmaf(a.w, wv.z, acc[3][2]); acc[3][3] = fmaf(a.w, wv.w, acc[3][3]);
    }
}
__device__ __forceinline__ void zero4(float acc[4][4]) {
#pragma unroll
    for (int i = 0; i < 4; i++)
#pragma unroll
        for (int c = 0; c < 4; c++) acc[i][c] = 0.f;
}
__device__ __forceinline__ void store4(float* dst, int stride, int r0, float acc[4][4]) {
#pragma unroll
    for (int i = 0; i < 4; i++)
        *(float4*)&dst[(r0 + i) * stride] =
            make_float4(acc[i][0], acc[i][1], acc[i][2], acc[i][3]);
}

extern "C" __global__ void __launch_bounds__(NT, 2) gru_kernel(
    const float* __restrict__ x, const float* __restrict__ y, const void* __restrict__ ymask,
    const float* __restrict__ Wmu1, const float* __restrict__ bmu1,
    const float* __restrict__ Wmu2, const float* __restrict__ bmu2,
    const float* __restrict__ Wih, const float* __restrict__ bih,
    const float* __restrict__ Whh, const float* __restrict__ bhh,
    const float* __restrict__ Wl1, const float* __restrict__ bl1,
    const float* __restrict__ Wl2, const float* __restrict__ bl2,
    const float* __restrict__ Wc1, const float* __restrict__ bc1,
    const float* __restrict__ Wc2, const float* __restrict__ bc2,
    float* __restrict__ out, int has_cls)
{
    extern __shared__ float sm[];
    const int tid  = threadIdx.x;
    const int lane = tid & 31;
    const int wid  = tid >> 5;        // 0..15
    const int role = wid >> 2;        // 0:r 1:z 2:nx(+h_r tail) 3:nh(+tails)
    const int r0   = (wid & 3) << 2;  // row quad base within <=16 rows
    const int b0   = (B_ * blockIdx.x) / NBK;
    const int nr   = (B_ * (blockIdx.x + 1)) / NBK - b0;   // 13 or 14 rows
    const int j0   = lane * 4;        // lanes<25 cover 100 cols

    // ---- stage biases + Wl1; zero y_prev ----
    for (int i = tid; i < G3; i += NT) { sm[OFF_BIH + i] = bih[i]; sm[OFF_BHH + i] = bhh[i]; }
    for (int i = tid; i < LAT; i += NT) sm[OFF_BL1 + i] = bl1[i];
    for (int i = tid; i < YD;  i += NT) sm[OFF_BL2 + i] = bl2[i];
    for (int i = tid; i < (LAT * LAT) / 4; i += NT)
        ((float4*)(sm + OFF_WL1))[i] = __ldg(((const float4*)Wl1) + i);
    for (int i = tid; i < YD * 17; i += NT) sm[OFF_YP + i] = 0.f;

    // ---- mask dtype detection (uint8 / int32 / float32), deterministic ----
    const unsigned word = ((const unsigned*)ymask)[tid];
    const int big = __syncthreads_or((word & 0xFEFEFEFEu) != 0u);  // any byte > 1 -> f32
    const int odd = __syncthreads_or((word & 0xFFFFFF00u) != 0u);  // upper bytes set -> u8
    const int mode = big ? 2 : (odd ? 0 : 1);

    // ---- stage x into AX ([k][16]); rows >= nr zeroed ----
#pragma unroll
    for (int i = 0; i < 4; i++) {
        const int e = tid + NT * i;       // 2048 = 16r x 128k
        const int r = e & 15, k = e >> 4;
        sm[OFF_AX + k * 16 + r] = (r < nr) ? __ldg(&x[(size_t)(b0 + r) * XD + k]) : 0.f;
    }
    __syncthreads();

    // ---- h0: tmp = tanh(x @ Wmu1 + bmu1) -> O1; h0 = tmp @ Wmu2 + bmu2 -> H ----
    if (lane < 25) {
        float acc[4] = {0.f, 0.f, 0.f, 0.f};
#pragma unroll 4
        for (int k = 0; k < XD; k++) {
            const float a = sm[OFF_AX + k * 16 + wid];
            const float4 wv = __ldg((const float4*)&Wmu1[k * LAT + j0]);
            acc[0] = fmaf(a, wv.x, acc[0]); acc[1] = fmaf(a, wv.y, acc[1]);
            acc[2] = fmaf(a, wv.z, acc[2]); acc[3] = fmaf(a, wv.w, acc[3]);
        }
        const float4 bb = __ldg((const float4*)&bmu1[j0]);
        sm[OFF_O1 + (j0 + 0) * 20 + wid] = ftanh_(acc[0] + bb.x);
        sm[OFF_O1 + (j0 + 1) * 20 + wid] = ftanh_(acc[1] + bb.y);
        sm[OFF_O1 + (j0 + 2) * 20 + wid] = ftanh_(acc[2] + bb.z);
        sm[OFF_O1 + (j0 + 3) * 20 + wid] = ftanh_(acc[3] + bb.w);
    }
    __syncthreads();
    if (lane < 25) {
        float acc[4] = {0.f, 0.f, 0.f, 0.f};
#pragma unroll 4
        for (int k = 0; k < LAT; k++) {
            const float a = sm[OFF_O1 + k * 20 + wid];
            const float4 wv = __ldg((const float4*)&Wmu2[k * LAT + j0]);
            acc[0] = fmaf(a, wv.x, acc[0]); acc[1] = fmaf(a, wv.y, acc[1]);
            acc[2] = fmaf(a, wv.z, acc[2]); acc[3] = fmaf(a, wv.w, acc[3]);
        }
        const float4 bb = __ldg((const float4*)&bmu2[j0]);
        sm[OFF_H + (j0 + 0) * 20 + wid] = acc[0] + bb.x;
        sm[OFF_H + (j0 + 1) * 20 + wid] = acc[1] + bb.y;
        sm[OFF_H + (j0 + 2) * 20 + wid] = acc[2] + bb.z;
        sm[OFF_H + (j0 + 3) * 20 + wid] = acc[3] + bb.w;
    }

    // ---- prefetch y/mask for t=0 ----
    float yv[2], mfv[2];
    auto preload = [&](int t) {
#pragma unroll
        for (int i = 0; i < 2; i++) {
            const int e = tid + NT * i;   // 1024 = 16r x 64d
            const int r = e & 15, d = e >> 4;
            if (r < nr) {
                const size_t off = (size_t)(b0 + r) * (YD * T_) + (size_t)d * T_ + t;
                yv[i] = __ldg(&y[off]);
                float m;
                if (mode == 0)      m = (((const unsigned char*)ymask)[off] != 0) ? 1.f : 0.f;
                else if (mode == 1) m = (((const int*)ymask)[off] != 0) ? 1.f : 0.f;
                else                m = (((const float*)ymask)[off] != 0.f) ? 1.f : 0.f;
                mfv[i] = m;
            } else { yv[i] = 0.f; mfv[i] = 0.f; }
        }
    };
    preload(0);
    __syncthreads();

    // ================= main recurrence =================
    for (int t = 0; t < T_; ++t) {
        // -- teacher forcing -> AX ([k][16], k interleaved value/mask) --
#pragma unroll
        for (int i = 0; i < 2; i++) {
            const int e = tid + NT * i;
            const int r = e & 15, d = e >> 4;
            const float m  = mfv[i];
            const float yp = sm[OFF_YP + d * 17 + r];
            const float yin = (m != 0.f) ? yv[i] : yp;
            sm[OFF_AX + (2 * d) * 16 + r]     = yin;
            sm[OFF_AX + (2 * d + 1) * 16 + r] = m;
        }
        if (t + 1 < T_) preload(t + 1);
        __syncthreads();

        // -- phase 1: balanced role segments (172/172/172/168 k-iters) --
        if (lane < 25) {
            float acc[4][4];
            zero4(acc);
            if (role == 0) {            // gate r: x full + h[0,44)
                accum(acc, sm + OFF_AX, 16, r0, Wih + j0, 0, XD);
                accum(acc, sm + OFF_H,  20, r0, Whh + j0, 0, 44);
                store4(sm + OFF_GX + j0, 304, r0, acc);
            } else if (role == 1) {     // gate z: x full + h[0,44)
                accum(acc, sm + OFF_AX, 16, r0, Wih + 100 + j0, 0, XD);
                accum(acc, sm + OFF_H,  20, r0, Whh + 100 + j0, 0, 44);
                store4(sm + OFF_GX + 100 + j0, 304, r0, acc);
            } else if (role == 2) {     // gate n x-part full; then h_r[44,88)
                accum(acc, sm + OFF_AX, 16, r0, Wih + 200 + j0, 0, XD);
                store4(sm + OFF_GX + 200 + j0, 304, r0, acc);
                zero4(acc);
                accum(acc, sm + OFF_H, 20, r0, Whh + j0, 44, 88);
                store4(sm + OFF_P2 + j0, 104, r0, acc);
            } else {                    // gate n h-part full; h_z[44,100); h_r[88,100)
                accum(acc, sm + OFF_H, 20, r0, Whh + 200 + j0, 0, LAT);
                store4(sm + OFF_GHN + j0, 104, r0, acc);
                zero4(acc);
                accum(acc, sm + OFF_H, 20, r0, Whh + 100 + j0, 44, LAT);
                store4(sm + OFF_P4 + j0, 104, r0, acc);
                zero4(acc);
                accum(acc, sm + OFF_H, 20, r0, Whh + j0, 88, LAT);
                store4(sm + OFF_P5 + j0, 104, r0, acc);
            }
        }
        __syncthreads();

        // -- gates: r,z = sigmoid; n = tanh(gxn + r*ghn); h = (1-z)*n + z*h --
#pragma unroll
        for (int it = 0; it < 4; ++it) {
            const int idx = tid + NT * it;    // 1600 = 16r x 100j
            if (idx < 16 * LAT) {
                const int r = idx / LAT;
                const int j = idx - r * LAT;
                const float g_r = sm[OFF_GX + r * 304 + j] + sm[OFF_P2 + r * 104 + j]
                                + sm[OFF_P5 + r * 104 + j]
                                + sm[OFF_BIH + j] + sm[OFF_BHH + j];
                const float g_z = sm[OFF_GX + r * 304 + 100 + j] + sm[OFF_P4 + r * 104 + j]
                                + sm[OFF_BIH + 100 + j] + sm[OFF_BHH + 100 + j];
                const float gxn = sm[OFF_GX + r * 304 + 200 + j] + sm[OFF_BIH + 200 + j];
                const float ghn = sm[OFF_GHN + r * 104 + j]      + sm[OFF_BHH + 200 + j];
                const float rg = fsig(g_r);
                const float z  = fsig(g_z);
                const float n  = ftanh_(gxn + rg * ghn);
                const float hd = sm[OFF_H + j * 20 + r];
                sm[OFF_H + j * 20 + r] = (1.f - z) * n + z * hd;
            }
        }
        __syncthreads();

        // -- GEMM3: o1 = tanh(h @ Wl1 + bl1); warp = row, Wl1 in SMEM --
        if (lane < 25) {
            float acc[4] = {0.f, 0.f, 0.f, 0.f};
#pragma unroll 4
            for (int k = 0; k < LAT; k++) {
                const float a = sm[OFF_H + k * 20 + wid];
                const float4 wv = *(const float4*)&sm[OFF_WL1 + k * LAT + j0];
                acc[0] = fmaf(a, wv.x, acc[0]); acc[1] = fmaf(a, wv.y, acc[1]);
                acc[2] = fmaf(a, wv.z, acc[2]); acc[3] = fmaf(a, wv.w, acc[3]);
            }
            const float4 bb = *(const float4*)&sm[OFF_BL1 + j0];
            sm[OFF_O1 + (j0 + 0) * 20 + wid] = ftanh_(acc[0] + bb.x);
            sm[OFF_O1 + (j0 + 1) * 20 + wid] = ftanh_(acc[1] + bb.y);
            sm[OFF_O1 + (j0 + 2) * 20 + wid] = ftanh_(acc[2] + bb.z);
            sm[OFF_O1 + (j0 + 3) * 20 + wid] = ftanh_(acc[3] + bb.w);
        }
        __syncthreads();

        // -- GEMM4: out_t = o1 @ Wl2 + bl2; warp = 4 cols, all lanes active --
        {
            const int row = lane & 15;                      // 0..15
            const int jc  = (wid << 2) + ((lane >> 4) << 1);// wid*4 + half*2
            float a0 = 0.f, a1 = 0.f;
#pragma unroll 4
            for (int k = 0; k < LAT; k++) {
                const float a = sm[OFF_O1 + k * 20 + row];
                const float2 wv = __ldg((const float2*)&Wl2[k * YD + jc]);
                a0 = fmaf(a, wv.x, a0); a1 = fmaf(a, wv.y, a1);
            }
            const float v0 = a0 + sm[OFF_BL2 + jc];
            const float v1 = a1 + sm[OFF_BL2 + jc + 1];
            if (row < nr) {
                float* op = out + (size_t)(b0 + row) * (YD * T_) + (size_t)jc * T_ + t;
                op[0]  = v0;
                op[T_] = v1;
            }
            sm[OFF_YP + jc * 17 + row]       = v0;
            sm[OFF_YP + (jc + 1) * 17 + row] = v1;
        }
        __syncthreads();
    }

    // ---- classifier: sigmoid(relu(h_T @ Wc1 + bc1) @ Wc2 + bc2) ----
    if (has_cls) {
        for (int idx = tid; idx < 16 * CH; idx += NT) {     // 800 = 16r x 50c
            const int r = idx & 15, c = idx >> 4;
            float acc = __ldg(&bc1[c]);
            for (int k = 0; k < LAT; k++)
                acc = fmaf(sm[OFF_H + k * 20 + r], __ldg(&Wc1[k * CH + c]), acc);
            sm[OFF_GHN + c * 16 + r] = fmaxf(acc, 0.f);
        }
        __syncthreads();
        if (tid < nr) {
            float acc = __ldg(&bc2[0]);
            for (int c = 0; c < CH; c++)
                acc = fmaf(sm[OFF_GHN + c * 16 + tid], __ldg(&Wc2[c]), acc);
            out[(size_t)B_ * YD * T_ + b0 + tid] = fsig(acc);
        }
    }
}

extern "C" void kernel_launch(void* const* d_in, const int* in_sizes, int n_in,
                              void* d_out, int out_size)
{
    cudaFuncSetAttribute(gru_kernel, cudaFuncAttributeMaxDynamicSharedMemorySize,
                         SMEM_FLOATS * (int)sizeof(float));
    const int has_cls = (out_size > B_ * YD * T_) ? 1 : 0;
    gru_kernel<<<NBK, NT, SMEM_FLOATS * sizeof(float)>>>(
        (const float*)d_in[0],   // x
        (const float*)d_in[1],   // y
        d_in[2],                 // y_mask (dtype auto-detected)
        (const float*)d_in[3],  (const float*)d_in[4],   // Wmu1, bmu1
        (const float*)d_in[5],  (const float*)d_in[6],   // Wmu2, bmu2
        (const float*)d_in[11], (const float*)d_in[12],  // Wih, bih
        (const float*)d_in[13], (const float*)d_in[14],  // Whh, bhh
        (const float*)d_in[15], (const float*)d_in[16],  // Wl1, bl1
        (const float*)d_in[17], (const float*)d_in[18],  // Wl2, bl2
        (const float*)d_in[19], (const float*)d_in[20],  // Wc1, bc1
        (const float*)d_in[21], (const float*)d_in[22],  // Wc2, bc2
        (float*)d_out, has_cls);
}